// round 1
// baseline (speedup 1.0000x reference)
#include <cuda_runtime.h>

#define FULL 0xffffffffu

// One warp per ray. 8 warps (256 threads) per block.
// Shared scratch per warp: coarse[64] | mids[64] | cdf[64] | fine[128] | merged[192] = 512 floats.
__global__ __launch_bounds__(256) void render_ray_kernel(
    const float* __restrict__ cdv,   // [B,64]  coarse depth values (sorted ascending)
    const float* __restrict__ cw,    // [B,64]  coarse weights
    const float* __restrict__ uin,   // [B,128] uniform samples
    const float* __restrict__ den,   // [B,192] raw density
    const float* __restrict__ col,   // [B,192,3] raw color
    float* __restrict__ out,         // [B,3]
    int B)
{
    const int warp = threadIdx.x >> 5;
    const int lane = threadIdx.x & 31;
    const int ray  = blockIdx.x * 8 + warp;
    if (ray >= B) return;

    __shared__ float sh[8][512];
    float* coarse = sh[warp];          // 64
    float* mids   = coarse + 64;       // 63 (pad 64)
    float* cdf    = mids + 64;         // 63 (pad 64)
    float* fine   = cdf + 64;          // 128
    float* merged = fine + 128;        // 192

    // ---- load coarse depths into shared ----
    const float* cdvp = cdv + (size_t)ray * 64;
    coarse[lane]      = cdvp[lane];
    coarse[32 + lane] = cdvp[32 + lane];
    __syncwarp();

    // ---- mids (63 bins edges) ----
    mids[lane] = 0.5f * (coarse[lane + 1] + coarse[lane]);
    if (lane < 31) mids[32 + lane] = 0.5f * (coarse[33 + lane] + coarse[32 + lane]);

    // ---- weights -> normalized CDF (62 pdf entries, cdf[0..62]) ----
    const float* cwp = cw + (size_t)ray * 64;
    float w0 = 0.f, w1 = 0.f;
    if (lane < 31) {                       // lanes 0..30 cover pdf indices 0..61
        w0 = cwp[1 + 2 * lane] + 1e-5f;    // coarse_weights[:,1:-1]
        w1 = cwp[2 + 2 * lane] + 1e-5f;
    }
    float s = w0 + w1;
    float inc = s;
    #pragma unroll
    for (int off = 1; off < 32; off <<= 1) {
        float v = __shfl_up_sync(FULL, inc, off);
        if (lane >= off) inc += v;
    }
    float total = __shfl_sync(FULL, inc, 31);
    float excl  = inc - s;
    float rt    = 1.0f / total;
    if (lane == 0) cdf[0] = 0.f;
    if (lane < 31) {
        cdf[2 * lane + 1] = (excl + w0) * rt;
        cdf[2 * lane + 2] = (excl + w0 + w1) * rt;
    }

    // ---- load u (4 per lane, blocked: element e = lane*4+j) and bitonic sort 128 ----
    const float4 u4 = reinterpret_cast<const float4*>(uin + (size_t)ray * 128)[lane];
    float r[4] = { u4.x, u4.y, u4.z, u4.w };
    const int ebase = lane * 4;

    #pragma unroll
    for (int k = 2; k <= 128; k <<= 1) {
        #pragma unroll
        for (int d = k >> 1; d > 0; d >>= 1) {
            if (d >= 4) {
                #pragma unroll
                for (int j = 0; j < 4; j++) {
                    int e = ebase + j;
                    float o = __shfl_xor_sync(FULL, r[j], d >> 2);
                    bool takeMin = (((e & k) == 0) != ((e & d) != 0));
                    r[j] = takeMin ? fminf(r[j], o) : fmaxf(r[j], o);
                }
            } else {
                #pragma unroll
                for (int j = 0; j < 4; j++) {
                    int jp = j ^ d;
                    if (jp > j) {
                        int e = ebase + j;
                        bool asc = ((e & k) == 0);
                        float lo2 = fminf(r[j], r[jp]);
                        float hi2 = fmaxf(r[j], r[jp]);
                        r[j]  = asc ? lo2 : hi2;
                        r[jp] = asc ? hi2 : lo2;
                    }
                }
            }
        }
    }

    __syncwarp();  // cdf, mids ready

    // ---- inverse CDF: sorted u -> sorted fine depths (monotone map) ----
    #pragma unroll
    for (int j = 0; j < 4; j++) {
        float uv = r[j];
        int lo = 0, hi = 62;                 // searchsorted(cdf[0..61], side='right')
        while (lo < hi) {
            int mid = (lo + hi) >> 1;
            if (cdf[mid] <= uv) lo = mid + 1; else hi = mid;
        }
        int above = lo;                      // in [1,62]
        int below = above - 1;
        float cb = cdf[below], ca = cdf[above];
        float bb = mids[below], ba = mids[above];
        float dnm = ca - cb;
        if (dnm < 1e-5f) dnm = 1.f;
        float t = (uv - cb) / dnm;
        fine[ebase + j] = bb + t * (ba - bb);
    }
    __syncwarp();

    // ---- merge-path: coarse[64] + fine[128] -> merged[192], 6 outputs/lane ----
    {
        const int d0 = lane * 6;
        int lo = max(0, d0 - 128), hi = min(d0, 64);
        while (lo < hi) {
            int i = (lo + hi) >> 1;
            if (coarse[i] <= fine[d0 - 1 - i]) lo = i + 1; else hi = i;
        }
        int ia = lo, jb = d0 - lo;
        #pragma unroll
        for (int t = 0; t < 6; t++) {
            float a = (ia < 64)  ? coarse[ia] : 3.0e38f;
            float b = (jb < 128) ? fine[jb]   : 3.0e38f;
            bool ta = (a <= b);
            merged[d0 + t] = ta ? a : b;
            ia += ta ? 1 : 0;
            jb += ta ? 0 : 1;
        }
    }
    __syncwarp();

    // ---- composite: alpha, cumprod transmittance (warp multiply-scan), color accum ----
    const float* denp = den + (size_t)ray * 192;
    const float* colp = col + (size_t)ray * 576;
    float C = 1.f;                 // running product of all previous chunks
    float aR = 0.f, aG = 0.f, aB = 0.f;

    #pragma unroll
    for (int k2 = 0; k2 < 6; k2++) {
        int idx = lane + 32 * k2;
        float dvv  = merged[idx];
        float dist = (idx == 191) ? 1e10f : (merged[idx + 1] - dvv);
        float x    = denp[idx] * dist;
        float ex   = __expf(-x);
        float alpha = 1.f - ex;
        float term  = ex + 1e-10f;           // = 1 - alpha + 1e-10

        float pin = term;                    // inclusive multiply-scan
        #pragma unroll
        for (int off = 1; off < 32; off <<= 1) {
            float v = __shfl_up_sync(FULL, pin, off);
            if (lane >= off) pin *= v;
        }
        float exclT = __shfl_up_sync(FULL, pin, 1);
        if (lane == 0) exclT = 1.f;
        float T   = C * exclT;
        float wgt = T * alpha;

        aR += wgt * colp[idx * 3 + 0];
        aG += wgt * colp[idx * 3 + 1];
        aB += wgt * colp[idx * 3 + 2];

        C *= __shfl_sync(FULL, pin, 31);
    }

    #pragma unroll
    for (int off = 16; off; off >>= 1) {
        aR += __shfl_down_sync(FULL, aR, off);
        aG += __shfl_down_sync(FULL, aG, off);
        aB += __shfl_down_sync(FULL, aB, off);
    }
    if (lane == 0) {
        out[(size_t)ray * 3 + 0] = aR;
        out[(size_t)ray * 3 + 1] = aG;
        out[(size_t)ray * 3 + 2] = aB;
    }
}

extern "C" void kernel_launch(void* const* d_in, const int* in_sizes, int n_in,
                              void* d_out, int out_size)
{
    // metadata order:
    // 0 ray_origin [B,3], 1 ray_direction [B,3], 2 coarse_depth_values [B,64],
    // 3 coarse_weights [B,64], 4 u [B,128], 5 raw_density [B,192,1], 6 raw_color [B,192,3]
    const float* cdv = (const float*)d_in[2];
    const float* cw  = (const float*)d_in[3];
    const float* u   = (const float*)d_in[4];
    const float* den = (const float*)d_in[5];
    const float* col = (const float*)d_in[6];
    float* out = (float*)d_out;
    const int B = in_sizes[0] / 3;

    const int warpsPerBlock = 8;
    const int blocks = (B + warpsPerBlock - 1) / warpsPerBlock;
    render_ray_kernel<<<blocks, warpsPerBlock * 32>>>(cdv, cw, u, den, col, out, B);
}

// round 3
// speedup vs baseline: 1.0703x; 1.0703x over previous
#include <cuda_runtime.h>

#define FULL 0xffffffffu

// One warp per ray, 8 warps/block.
// Shared per warp: [0..63]=coarse, [64..127]=mids, [128..191]=cdf, [192..319]=fine.
// After merge, [0..191] is reused for per-sample weights.
__global__ __launch_bounds__(256) void render_ray_kernel(
    const float* __restrict__ cdv,   // [B,64]
    const float* __restrict__ cw,    // [B,64]
    const float* __restrict__ uin,   // [B,128]
    const float* __restrict__ den,   // [B,192]
    const float* __restrict__ col,   // [B,192,3]
    float* __restrict__ out,         // [B,3]
    int B)
{
    const int warp = threadIdx.x >> 5;
    const int lane = threadIdx.x & 31;
    const int ray  = blockIdx.x * 8 + warp;
    if (ray >= B) return;

    __shared__ float sh[8][320];
    float* base   = sh[warp];
    float* coarse = base;          // 64
    float* mids   = base + 64;     // 63
    float* cdf    = base + 128;    // 63
    float* fineS  = base + 192;    // 128
    float* wsh    = base;          // 192 (reuse after merge)

    // ---- coarse depths: one LDG.64 per lane, mids via neighbor shuffle ----
    const float2 c2 = reinterpret_cast<const float2*>(cdv + (size_t)ray * 64)[lane];
    reinterpret_cast<float2*>(coarse)[lane] = c2;
    {
        float nx = __shfl_down_sync(FULL, c2.x, 1);
        mids[2 * lane] = 0.5f * (c2.x + c2.y);
        if (lane < 31) mids[2 * lane + 1] = 0.5f * (c2.y + nx);
    }

    // ---- weights -> normalized CDF (62 pdf entries, cdf[0..62]) ----
    const float* cwp = cw + (size_t)ray * 64;
    float w0 = 0.f, w1 = 0.f;
    if (lane < 31) {
        w0 = cwp[1 + 2 * lane] + 1e-5f;
        w1 = cwp[2 + 2 * lane] + 1e-5f;
    }
    float s2 = w0 + w1;
    float inc = s2;
    #pragma unroll
    for (int off = 1; off < 32; off <<= 1) {
        float v = __shfl_up_sync(FULL, inc, off);
        if (lane >= off) inc += v;
    }
    float total = __shfl_sync(FULL, inc, 31);
    float excl0 = inc - s2;
    float rt    = 1.0f / total;
    if (lane == 0) cdf[0] = 0.f;
    if (lane < 31) {
        cdf[2 * lane + 1] = (excl0 + w0) * rt;
        cdf[2 * lane + 2] = (excl0 + w0 + w1) * rt;
    }

    // ---- load u (4/lane blocked) and bitonic sort 128 ----
    const float4 u4 = reinterpret_cast<const float4*>(uin + (size_t)ray * 128)[lane];
    float r[4] = { u4.x, u4.y, u4.z, u4.w };
    const int ebase = lane * 4;

    #pragma unroll
    for (int k = 2; k <= 128; k <<= 1) {
        #pragma unroll
        for (int d = k >> 1; d > 0; d >>= 1) {
            if (d >= 4) {
                // direction depends only on lane bits for k>=8,d>=4
                const bool flip = (((ebase & k) == 0) != ((ebase & d) != 0));
                #pragma unroll
                for (int j = 0; j < 4; j++) {
                    float o = __shfl_xor_sync(FULL, r[j], d >> 2);
                    r[j] = flip ? fminf(r[j], o) : fmaxf(r[j], o);
                }
            } else {
                #pragma unroll
                for (int j = 0; j < 4; j++) {
                    int jp = j ^ d;
                    if (jp > j) {
                        bool asc = (((ebase + j) & k) == 0);
                        float lo2 = fminf(r[j], r[jp]);
                        float hi2 = fmaxf(r[j], r[jp]);
                        r[j]  = asc ? lo2 : hi2;
                        r[jp] = asc ? hi2 : lo2;
                    }
                }
            }
        }
    }

    __syncwarp();  // cdf, mids, coarse visible

    // ---- inverse CDF: sorted u -> sorted fine depths ----
    #pragma unroll
    for (int j = 0; j < 4; j++) {
        float uv = r[j];
        int lo = 0, hi = 62;
        while (lo < hi) {
            int mid = (lo + hi) >> 1;
            if (cdf[mid] <= uv) lo = mid + 1; else hi = mid;
        }
        int above = lo, below = lo - 1;
        float cb = cdf[below], ca = cdf[above];
        float bb = mids[below], ba = mids[above];
        float dnm = ca - cb;
        if (dnm < 1e-5f) dnm = 1.f;
        float t = (uv - cb) / dnm;
        fineS[ebase + j] = bb + t * (ba - bb);
    }
    __syncwarp();

    // ---- merge-path: coarse[64] + fine[128] -> 6 register outputs/lane ----
    float m[6];
    {
        const int d0 = lane * 6;
        int lo = max(0, d0 - 128), hi = min(d0, 64);
        while (lo < hi) {
            int i = (lo + hi) >> 1;
            if (coarse[i] <= fineS[d0 - 1 - i]) lo = i + 1; else hi = i;
        }
        int ia = lo, jb = d0 - lo;
        #pragma unroll
        for (int t = 0; t < 6; t++) {
            float a = (ia < 64)  ? coarse[ia] : 3.0e38f;
            float b = (jb < 128) ? fineS[jb]  : 3.0e38f;
            bool ta = (a <= b);
            m[t] = ta ? a : b;
            ia += ta ? 1 : 0;
            jb += ta ? 0 : 1;
        }
    }
    __syncwarp();   // all coarse/fine reads done; base[] safe to reuse

    // next lane's first element for the boundary dist
    float m6 = __shfl_down_sync(FULL, m[0], 1);

    // ---- densities: blocked, 3x LDG.64 per lane ----
    const float* dp = den + (size_t)ray * 192 + 6 * lane;
    float2 d01 = reinterpret_cast<const float2*>(dp)[0];
    float2 d23 = reinterpret_cast<const float2*>(dp + 2)[0];
    float2 d45 = reinterpret_cast<const float2*>(dp + 4)[0];

    // x_t = density * dist, local inclusive prefix
    float x0 = d01.x * (m[1] - m[0]);
    float x1 = x0 + d01.y * (m[2] - m[1]);
    float x2 = x1 + d23.x * (m[3] - m[2]);
    float x3 = x2 + d23.y * (m[4] - m[3]);
    float x4 = x3 + d45.x * (m[5] - m[4]);
    float lastDist = (lane == 31) ? 1e10f : (m6 - m[5]);
    float x5 = x4 + d45.y * lastDist;

    // Scan value: for lane 31 exclude the artificial 1e10 term (nobody consumes
    // lane 31's scan output; including ~1e10 causes catastrophic cancellation
    // in Sx = tinc - xs). e5 below still uses the full x5 (exp -> 0).
    float xs = (lane == 31) ? x4 : x5;

    // warp inclusive scan over lane totals
    float tinc = xs;
    #pragma unroll
    for (int off = 1; off < 32; off <<= 1) {
        float v = __shfl_up_sync(FULL, tinc, off);
        if (lane >= off) tinc += v;
    }
    float Sx = tinc - xs;   // exclusive offset for this lane (sum of lanes < me)

    // weights: w_i = exp(-S_{i-1}) - exp(-S_i)
    float e0p = __expf(-Sx);
    float e0 = __expf(-(Sx + x0));
    float e1 = __expf(-(Sx + x1));
    float e2 = __expf(-(Sx + x2));
    float e3 = __expf(-(Sx + x3));
    float e4 = __expf(-(Sx + x4));
    float e5 = __expf(-(Sx + x5));

    const int wb = 6 * lane;
    wsh[wb + 0] = e0p - e0;
    wsh[wb + 1] = e0 - e1;
    wsh[wb + 2] = e1 - e2;
    wsh[wb + 3] = e2 - e3;
    wsh[wb + 4] = e3 - e4;
    wsh[wb + 5] = e4 - e5;
    __syncwarp();

    // ---- color accumulation: coalesced loads + phase-rotated accumulators ----
    const float* colp = col + (size_t)ray * 576;
    float a0 = 0.f, a1 = 0.f, a2 = 0.f;
    #pragma unroll
    for (int t = 0; t < 18; t++) {
        unsigned j = 32u * t + lane;
        float v = colp[j];
        float wv = wsh[j / 3u];
        const int k = (2 * t) % 3;   // compile-time
        if (k == 0) a0 += wv * v;
        else if (k == 1) a1 += wv * v;
        else a2 += wv * v;
    }

    // lane's a[k] holds color component (p + k) % 3, p = lane % 3
    const int p = lane % 3;
    float rr = (p == 0) ? a0 : ((p == 1) ? a2 : a1);
    float gg = (p == 0) ? a1 : ((p == 1) ? a0 : a2);
    float bb = (p == 0) ? a2 : ((p == 1) ? a1 : a0);

    #pragma unroll
    for (int off = 16; off; off >>= 1) {
        rr += __shfl_down_sync(FULL, rr, off);
        gg += __shfl_down_sync(FULL, gg, off);
        bb += __shfl_down_sync(FULL, bb, off);
    }
    if (lane == 0) {
        out[(size_t)ray * 3 + 0] = rr;
        out[(size_t)ray * 3 + 1] = gg;
        out[(size_t)ray * 3 + 2] = bb;
    }
}

extern "C" void kernel_launch(void* const* d_in, const int* in_sizes, int n_in,
                              void* d_out, int out_size)
{
    const float* cdv = (const float*)d_in[2];
    const float* cw  = (const float*)d_in[3];
    const float* u   = (const float*)d_in[4];
    const float* den = (const float*)d_in[5];
    const float* col = (const float*)d_in[6];
    float* out = (float*)d_out;
    const int B = in_sizes[0] / 3;

    const int warpsPerBlock = 8;
    const int blocks = (B + warpsPerBlock - 1) / warpsPerBlock;
    render_ray_kernel<<<blocks, warpsPerBlock * 32>>>(cdv, cw, u, den, col, out, B);
}

// round 5
// speedup vs baseline: 1.1697x; 1.0929x over previous
#include <cuda_runtime.h>
#include <math_constants.h>

#define FULL 0xffffffffu

// One warp per ray, 8 warps/block.
// Per-warp smem words: [0..63]=coarse, [64]=INF sentinel, [65..127]=cdf(63),
// [192..319]=fine, [320]=INF sentinel. After merge, [0..191] reused as weights.
__global__ __launch_bounds__(256) void render_ray_kernel(
    const float* __restrict__ cdv,   // [B,64]
    const float* __restrict__ cw,    // [B,64]
    const float* __restrict__ uin,   // [B,128]
    const float* __restrict__ den,   // [B,192]
    const float* __restrict__ col,   // [B,192,3]
    float* __restrict__ out,         // [B,3]
    int B)
{
    const int warp = threadIdx.x >> 5;
    const int lane = threadIdx.x & 31;
    const int ray  = blockIdx.x * 8 + warp;
    if (ray >= B) return;

    __shared__ float sh[8][328];
    float* base  = sh[warp];
    float* cdfs  = base + 65;     // cdf[0..62]
    float* fineS = base + 192;    // 128 + sentinel at 320
    float* wsh   = base;          // 192 weights (reuse after merge)

    // ---- coarse depths: one LDG.64 per lane into smem; uniform-grid params ----
    const float2 c2 = reinterpret_cast<const float2*>(cdv + (size_t)ray * 64)[lane];
    reinterpret_cast<float2*>(base)[lane] = c2;
    const float NEARv = __shfl_sync(FULL, c2.x, 0);
    const float step  = __shfl_sync(FULL, c2.y, 0) - NEARv;
    const float M0    = NEARv + 0.5f * step;     // mids[k] ~= M0 + k*step
    if (lane == 0) base[64]  = CUDART_INF_F;     // coarse sentinel
    if (lane == 1) base[320] = CUDART_INF_F;     // fine sentinel

    // ---- weights -> normalized CDF (62 pdf entries, cdf[0..62]) ----
    const float* cwp = cw + (size_t)ray * 64;
    float w0 = 0.f, w1 = 0.f;
    if (lane < 31) {
        w0 = cwp[1 + 2 * lane] + 1e-5f;
        w1 = cwp[2 + 2 * lane] + 1e-5f;
    }
    float s2 = w0 + w1;
    float inc = s2;
    #pragma unroll
    for (int off = 1; off < 32; off <<= 1) {
        float v = __shfl_up_sync(FULL, inc, off);
        if (lane >= off) inc += v;
    }
    float total = __shfl_sync(FULL, inc, 31);
    float excl0 = inc - s2;
    float rt    = __fdividef(1.0f, total);
    if (lane == 0) cdfs[0] = 0.f;
    if (lane < 31) {
        cdfs[2 * lane + 1] = (excl0 + w0) * rt;
        cdfs[2 * lane + 2] = (excl0 + w0 + w1) * rt;
    }

    // ---- load u (4/lane blocked) and bitonic sort 128 ----
    const float4 u4 = reinterpret_cast<const float4*>(uin + (size_t)ray * 128)[lane];
    float r[4] = { u4.x, u4.y, u4.z, u4.w };
    const int ebase = lane * 4;

    #pragma unroll
    for (int k = 2; k <= 128; k <<= 1) {
        #pragma unroll
        for (int d = k >> 1; d > 0; d >>= 1) {
            if (d >= 4) {
                const bool flip = (((ebase & k) == 0) != ((ebase & d) != 0));
                #pragma unroll
                for (int j = 0; j < 4; j++) {
                    float o = __shfl_xor_sync(FULL, r[j], d >> 2);
                    r[j] = flip ? fminf(r[j], o) : fmaxf(r[j], o);
                }
            } else {
                #pragma unroll
                for (int j = 0; j < 4; j++) {
                    int jp = j ^ d;
                    if (jp > j) {
                        bool asc = (((ebase + j) & k) == 0);
                        float lo2 = fminf(r[j], r[jp]);
                        float hi2 = fmaxf(r[j], r[jp]);
                        r[j]  = asc ? lo2 : hi2;
                        r[jp] = asc ? hi2 : lo2;
                    }
                }
            }
        }
    }

    __syncwarp();  // cdf, coarse, sentinels visible

    // ---- inverse CDF: sorted u -> sorted fine depths (6 branchless probes) ----
    // width 62 closes in exactly 6 probes: 62->31->15->7->3->1->0
    #pragma unroll
    for (int j = 0; j < 4; j++) {
        float uv = r[j];
        int lo = 0, hi = 62;                  // answer (count of cdf[0..61] <= u)
        #pragma unroll
        for (int it = 0; it < 6; it++) {
            int mid = (lo + hi) >> 1;
            float cv = cdfs[mid];
            bool open = (lo < hi);
            bool gt   = open && (cv <= uv);
            bool le   = open && !(cv <= uv);
            lo = gt ? mid + 1 : lo;
            hi = le ? mid : hi;
        }
        int above = lo;                       // in [1,62]
        float cb = cdfs[above - 1];
        float ca = cdfs[above];
        float dnm = ca - cb;
        if (dnm < 1e-5f) dnm = 1.f;
        float t = __fdividef(uv - cb, dnm);
        fineS[ebase + j] = fmaf(__int2float_rn(above - 1) + t, step, M0);
    }
    __syncwarp();

    // ---- merge-path: coarse[64] + fine[128] -> 6 register outputs/lane ----
    float m[6];
    {
        const int d0 = lane * 6;
        int lo = max(0, d0 - 128), hi = min(d0, 64);
        #pragma unroll
        for (int it = 0; it < 7; it++) {      // width <= 64 -> 7 guarded probes
            int mid = (lo + hi) >> 1;
            float a = base[mid];
            float b = base[192 + d0 - 1 - mid];
            bool open = (lo < hi);
            bool gt   = open && (a <= b);
            bool le   = open && !(a <= b);
            lo = gt ? mid + 1 : lo;
            hi = le ? mid : hi;
        }
        int ia = lo;                // smem index into coarse (0..64)
        int jb = 192 + (d0 - lo);   // smem index into fine   (192..320)
        float a = base[ia];
        float b = base[jb];
        #pragma unroll
        for (int t = 0; t < 6; t++) {
            bool ta = (a <= b);
            m[t] = ta ? a : b;
            int nidx = ta ? (ia + 1) : (jb + 1);
            float nv = base[nidx];
            ia = ta ? nidx : ia;
            jb = ta ? jb : nidx;
            a = ta ? nv : a;
            b = ta ? b : nv;
        }
    }
    __syncwarp();   // all coarse/fine reads done; base[] safe to reuse

    float m6 = __shfl_down_sync(FULL, m[0], 1);

    // ---- densities: blocked, 3x LDG.64 per lane ----
    const float* dp = den + (size_t)ray * 192 + 6 * lane;
    float2 d01 = reinterpret_cast<const float2*>(dp)[0];
    float2 d23 = reinterpret_cast<const float2*>(dp + 2)[0];
    float2 d45 = reinterpret_cast<const float2*>(dp + 4)[0];

    float x0 = d01.x * (m[1] - m[0]);
    float x1 = x0 + d01.y * (m[2] - m[1]);
    float x2 = x1 + d23.x * (m[3] - m[2]);
    float x3 = x2 + d23.y * (m[4] - m[3]);
    float x4 = x3 + d45.x * (m[5] - m[4]);
    float lastDist = (lane == 31) ? 1e10f : (m6 - m[5]);
    float x5 = x4 + d45.y * lastDist;

    // Lane 31: exclude the artificial 1e10 term from the scan value
    // (prevents catastrophic cancellation in Sx; e5 still uses full x5 -> 0).
    float xs = (lane == 31) ? x4 : x5;

    float tinc = xs;
    #pragma unroll
    for (int off = 1; off < 32; off <<= 1) {
        float v = __shfl_up_sync(FULL, tinc, off);
        if (lane >= off) tinc += v;
    }
    float Sx = tinc - xs;   // exclusive prefix (sum of lanes < me)

    float e0p = __expf(-Sx);
    float e0 = __expf(-(Sx + x0));
    float e1 = __expf(-(Sx + x1));
    float e2 = __expf(-(Sx + x2));
    float e3 = __expf(-(Sx + x3));
    float e4 = __expf(-(Sx + x4));
    float e5 = __expf(-(Sx + x5));

    const int wb = 6 * lane;
    wsh[wb + 0] = e0p - e0;
    wsh[wb + 1] = e0 - e1;
    wsh[wb + 2] = e1 - e2;
    wsh[wb + 3] = e2 - e3;
    wsh[wb + 4] = e3 - e4;
    wsh[wb + 5] = e4 - e5;
    __syncwarp();

    // ---- color accumulation: coalesced loads, div-free weight indexing ----
    // j = 32t + lane = 3*(10t + (2t)/3 + L) + ((2t)%3 + p)
    // floor(j/3) = 10t + (2t)/3 + L + carry, carry = ((2t)%3 + p >= 3)
    const int L  = lane / 3;          // lane = 3L + p
    const int p  = lane - 3 * L;
    const float* wp0 = wsh + L;                 // R=0: carry always 0
    const float* wp1 = wsh + L + (p >= 1);      // R=2: carry = (p>=1)
    const float* wp2 = wsh + L + (p >= 2);      // R=1: carry = (p>=2)

    const float* colp = col + (size_t)ray * 576;
    float a0 = 0.f, a1 = 0.f, a2 = 0.f;
    #pragma unroll
    for (int t = 0; t < 18; t++) {
        float v = colp[32 * t + lane];
        const int R = (2 * t) % 3;              // compile-time
        const int C = 10 * t + (2 * t) / 3;     // compile-time (includes the 10t term!)
        float wv = (R == 0) ? wp0[C] : ((R == 1) ? wp2[C] : wp1[C]);
        if (R == 0) a0 += wv * v;
        else if (R == 1) a1 += wv * v;
        else a2 += wv * v;
    }

    // lane's a[k] holds color component (p + k) % 3
    float rr = (p == 0) ? a0 : ((p == 1) ? a2 : a1);
    float gg = (p == 0) ? a1 : ((p == 1) ? a0 : a2);
    float bb = (p == 0) ? a2 : ((p == 1) ? a1 : a0);

    #pragma unroll
    for (int off = 16; off; off >>= 1) {
        rr += __shfl_down_sync(FULL, rr, off);
        gg += __shfl_down_sync(FULL, gg, off);
        bb += __shfl_down_sync(FULL, bb, off);
    }
    if (lane == 0) {
        out[(size_t)ray * 3 + 0] = rr;
        out[(size_t)ray * 3 + 1] = gg;
        out[(size_t)ray * 3 + 2] = bb;
    }
}

extern "C" void kernel_launch(void* const* d_in, const int* in_sizes, int n_in,
                              void* d_out, int out_size)
{
    const float* cdv = (const float*)d_in[2];
    const float* cw  = (const float*)d_in[3];
    const float* u   = (const float*)d_in[4];
    const float* den = (const float*)d_in[5];
    const float* col = (const float*)d_in[6];
    float* out = (float*)d_out;
    const int B = in_sizes[0] / 3;

    const int warpsPerBlock = 8;
    const int blocks = (B + warpsPerBlock - 1) / warpsPerBlock;
    render_ray_kernel<<<blocks, warpsPerBlock * 32>>>(cdv, cw, u, den, col, out, B);
}

// round 6
// speedup vs baseline: 1.2950x; 1.1071x over previous
#include <cuda_runtime.h>
#include <math_constants.h>

#define FULL 0xffffffffu

// One warp per ray, 8 warps/block.
// Per-warp smem words: [0..62]=cdf, [63]=INF, [64..191]=fine, [192]=INF.
// After merge, [0..191] reused as per-sample weights.
__global__ __launch_bounds__(256) void render_ray_kernel(
    const float* __restrict__ cdv,   // [B,64] uniform grid NEAR + k*step
    const float* __restrict__ cw,    // [B,64]
    const float* __restrict__ uin,   // [B,128]
    const float* __restrict__ den,   // [B,192]
    const float* __restrict__ col,   // [B,192,3]
    float* __restrict__ out,         // [B,3]
    int B)
{
    const int warp = threadIdx.x >> 5;
    const int lane = threadIdx.x & 31;
    const int ray  = blockIdx.x * 8 + warp;
    if (ray >= B) return;

    __shared__ float sh[8][200];
    float* base  = sh[warp];
    float* cdfs  = base;          // cdf[0..62], [63]=INF sentinel
    float* fineS = base + 64;     // fine[0..127], sentinel at base[192]
    float* wsh   = base;          // 192 weights (reuse after merge)

    // ---- uniform grid params: only cdv[0], cdv[1] needed ----
    float2 c2 = make_float2(0.f, 0.f);
    if (lane == 0) c2 = *reinterpret_cast<const float2*>(cdv + (size_t)ray * 64);
    const float NEARv = __shfl_sync(FULL, c2.x, 0);
    const float step  = __shfl_sync(FULL, c2.y, 0) - NEARv;
    const float M0    = NEARv + 0.5f * step;     // mids[k] = M0 + k*step
    if (lane == 0) cdfs[63]  = CUDART_INF_F;     // cdf pad for unguarded search
    if (lane == 1) base[192] = CUDART_INF_F;     // fine sentinel

    // ---- weights -> normalized CDF (62 pdf entries, cdf[0..62]) ----
    const float* cwp = cw + (size_t)ray * 64;
    float w0 = 0.f, w1 = 0.f;
    if (lane < 31) {
        w0 = cwp[1 + 2 * lane] + 1e-5f;
        w1 = cwp[2 + 2 * lane] + 1e-5f;
    }
    float s2 = w0 + w1;
    float inc = s2;
    #pragma unroll
    for (int off = 1; off < 32; off <<= 1) {
        float v = __shfl_up_sync(FULL, inc, off);
        if (lane >= off) inc += v;
    }
    float total = __shfl_sync(FULL, inc, 31);
    float excl0 = inc - s2;
    float rt    = __fdividef(1.0f, total);
    if (lane == 0) cdfs[0] = 0.f;
    if (lane < 31) {
        cdfs[2 * lane + 1] = (excl0 + w0) * rt;
        cdfs[2 * lane + 2] = (excl0 + w0 + w1) * rt;
    }

    // ---- load u (4/lane blocked) and bitonic sort 128 ----
    const float4 u4 = reinterpret_cast<const float4*>(uin + (size_t)ray * 128)[lane];
    float r[4] = { u4.x, u4.y, u4.z, u4.w };
    const int ebase = lane * 4;

    #pragma unroll
    for (int k = 2; k <= 128; k <<= 1) {
        #pragma unroll
        for (int d = k >> 1; d > 0; d >>= 1) {
            if (d >= 4) {
                const bool flip = (((ebase & k) == 0) != ((ebase & d) != 0));
                #pragma unroll
                for (int j = 0; j < 4; j++) {
                    float o = __shfl_xor_sync(FULL, r[j], d >> 2);
                    r[j] = flip ? fminf(r[j], o) : fmaxf(r[j], o);
                }
            } else {
                #pragma unroll
                for (int j = 0; j < 4; j++) {
                    int jp = j ^ d;
                    if (jp > j) {
                        bool asc = (((ebase + j) & k) == 0);
                        float lo2 = fminf(r[j], r[jp]);
                        float hi2 = fmaxf(r[j], r[jp]);
                        r[j]  = asc ? lo2 : hi2;
                        r[jp] = asc ? hi2 : lo2;
                    }
                }
            }
        }
    }

    __syncwarp();  // cdf + sentinels visible

    // ---- inverse CDF: unguarded power-of-2 count search (6 probes) ----
    // counts entries of cdf[0..62] <= u; cdf[63]=INF pad. c >= 1 since cdf[0]=0.
    #pragma unroll
    for (int j = 0; j < 4; j++) {
        float uv = r[j];
        int c = 0;
        #pragma unroll
        for (int w = 32; w; w >>= 1)
            c += (cdfs[c + w - 1] <= uv) ? w : 0;
        float cb = cdfs[c - 1];
        float ca = cdfs[c];               // c==63 -> INF -> t==0, clamps to last mid
        float dnm = ca - cb;
        if (dnm < 1e-5f) dnm = 1.f;
        float t = __fdividef(uv - cb, dnm);
        fineS[ebase + j] = fmaf(__int2float_rn(c - 1) + t, step, M0);
    }
    __syncwarp();

    // ---- merge-path: arithmetic coarse (NEAR + i*step) + fine[128] -> 6 regs ----
    float m[6];
    {
        const int d0  = lane * 6;
        const int hib = min(d0, 64);
        int c = max(0, d0 - 128);
        #pragma unroll
        for (int w = 64; w; w >>= 1) {
            int idx = c + w - 1;
            float a = fmaf(__int2float_rn(idx), step, NEARv);
            float b = base[64 + d0 - 1 - idx];   // in-bounds; junk guarded below
            bool ok = (idx < hib) && (a <= b);
            c += ok ? w : 0;
        }
        int jb = d0 - c;                 // fine cursor (0..128)
        float fia = __int2float_rn(c);   // coarse cursor as float
        float a = fmaf(fia, step, NEARv);   // index 64 acts as natural sentinel (> all fine)
        float b = base[64 + jb];            // jb==128 -> INF sentinel
        #pragma unroll
        for (int t = 0; t < 6; t++) {
            bool ta = (a <= b);
            m[t] = ta ? a : b;
            fia += ta ? 1.0f : 0.0f;
            jb  += ta ? 0 : 1;
            a = fmaf(fia, step, NEARv);
            b = base[64 + jb];
        }
    }
    __syncwarp();   // all fine reads done; base[] safe to reuse

    float m6 = __shfl_down_sync(FULL, m[0], 1);

    // ---- densities: blocked, 3x LDG.64 per lane ----
    const float* dp = den + (size_t)ray * 192 + 6 * lane;
    float2 d01 = reinterpret_cast<const float2*>(dp)[0];
    float2 d23 = reinterpret_cast<const float2*>(dp + 2)[0];
    float2 d45 = reinterpret_cast<const float2*>(dp + 4)[0];

    float x0 = d01.x * (m[1] - m[0]);
    float x1 = x0 + d01.y * (m[2] - m[1]);
    float x2 = x1 + d23.x * (m[3] - m[2]);
    float x3 = x2 + d23.y * (m[4] - m[3]);
    float x4 = x3 + d45.x * (m[5] - m[4]);
    float lastDist = (lane == 31) ? 1e10f : (m6 - m[5]);
    float x5 = x4 + d45.y * lastDist;

    // Lane 31: exclude the artificial 1e10 term from the scan value
    // (prevents catastrophic cancellation in Sx; e5 still uses full x5 -> 0).
    float xs = (lane == 31) ? x4 : x5;

    float tinc = xs;
    #pragma unroll
    for (int off = 1; off < 32; off <<= 1) {
        float v = __shfl_up_sync(FULL, tinc, off);
        if (lane >= off) tinc += v;
    }
    float Sx = tinc - xs;   // exclusive prefix (sum of lanes < me)

    float e0p = __expf(-Sx);
    float e0 = __expf(-(Sx + x0));
    float e1 = __expf(-(Sx + x1));
    float e2 = __expf(-(Sx + x2));
    float e3 = __expf(-(Sx + x3));
    float e4 = __expf(-(Sx + x4));
    float e5 = __expf(-(Sx + x5));

    const int wb = 6 * lane;
    wsh[wb + 0] = e0p - e0;
    wsh[wb + 1] = e0 - e1;
    wsh[wb + 2] = e1 - e2;
    wsh[wb + 3] = e2 - e3;
    wsh[wb + 4] = e3 - e4;
    wsh[wb + 5] = e4 - e5;
    __syncwarp();

    // ---- color accumulation: coalesced loads, div-free weight indexing ----
    // j = 32t + lane; floor(j/3) = 10t + (2t)/3 + L + carry
    const int L  = lane / 3;          // lane = 3L + p
    const int p  = lane - 3 * L;
    const float* wp0 = wsh + L;                 // R=0: carry 0
    const float* wp1 = wsh + L + (p >= 1);      // R=2: carry = (p>=1)
    const float* wp2 = wsh + L + (p >= 2);      // R=1: carry = (p>=2)

    const float* colp = col + (size_t)ray * 576;
    float a0 = 0.f, a1 = 0.f, a2 = 0.f;
    #pragma unroll
    for (int t = 0; t < 18; t++) {
        float v = colp[32 * t + lane];
        const int R = (2 * t) % 3;              // compile-time
        const int C = 10 * t + (2 * t) / 3;     // compile-time
        float wv = (R == 0) ? wp0[C] : ((R == 1) ? wp2[C] : wp1[C]);
        if (R == 0) a0 += wv * v;
        else if (R == 1) a1 += wv * v;
        else a2 += wv * v;
    }

    // lane's a[k] holds color component (p + k) % 3
    float rr = (p == 0) ? a0 : ((p == 1) ? a2 : a1);
    float gg = (p == 0) ? a1 : ((p == 1) ? a0 : a2);
    float bb = (p == 0) ? a2 : ((p == 1) ? a1 : a0);

    #pragma unroll
    for (int off = 16; off; off >>= 1) {
        rr += __shfl_down_sync(FULL, rr, off);
        gg += __shfl_down_sync(FULL, gg, off);
        bb += __shfl_down_sync(FULL, bb, off);
    }
    if (lane == 0) {
        out[(size_t)ray * 3 + 0] = rr;
        out[(size_t)ray * 3 + 1] = gg;
        out[(size_t)ray * 3 + 2] = bb;
    }
}

extern "C" void kernel_launch(void* const* d_in, const int* in_sizes, int n_in,
                              void* d_out, int out_size)
{
    const float* cdv = (const float*)d_in[2];
    const float* cw  = (const float*)d_in[3];
    const float* u   = (const float*)d_in[4];
    const float* den = (const float*)d_in[5];
    const float* col = (const float*)d_in[6];
    float* out = (float*)d_out;
    const int B = in_sizes[0] / 3;

    const int warpsPerBlock = 8;
    const int blocks = (B + warpsPerBlock - 1) / warpsPerBlock;
    render_ray_kernel<<<blocks, warpsPerBlock * 32>>>(cdv, cw, u, den, col, out, B);
}